// round 4
// baseline (speedup 1.0000x reference)
#include <cuda_runtime.h>
#include <cuda_bf16.h>

#define DD 4096
#define NSM 148
#define THREADS 1024
#define MATSZ ((size_t)DD * DD)

// ping-pong node buffers (scatter idx is a permutation -> fully overwritten each layer)
__device__ float g_buf0[DD];
__device__ float g_buf1[DD];
// self-resetting grid-barrier slots (zero-initialized at module load; each launch leaves them zero)
__device__ unsigned g_arr[8];
__device__ unsigned g_dep[8];

__device__ __forceinline__ void prefetch_l2(const void* p) {
    asm volatile("prefetch.global.L2 [%0];" :: "l"(p));
}

__device__ __forceinline__ void grid_barrier(int slot) {
    __syncthreads();
    if (threadIdx.x == 0) {
        __threadfence();                       // publish this block's scatter stores
        atomicAdd(&g_arr[slot], 1u);
        while (*(volatile unsigned*)&g_arr[slot] < NSM) __nanosleep(32);
        __threadfence();                       // acquire + L1D invalidate (gpu scope)
        unsigned d = atomicAdd(&g_dep[slot], 1u);
        if (d == NSM - 1u) {                   // last departer resets for next graph replay
            *(volatile unsigned*)&g_dep[slot] = 0u;
            *(volatile unsigned*)&g_arr[slot] = 0u;
        }
    }
    __syncthreads();
}

__global__ __launch_bounds__(THREADS, 1)
void net_fused(const float* __restrict__ x,
               const float* __restrict__ W_in,
               const float* __restrict__ b_in,
               const float* __restrict__ weights,
               const float* __restrict__ orders,
               const float* __restrict__ biases,
               const int*   __restrict__ gidx,
               const int*   __restrict__ sidx,
               float*       __restrict__ out)
{
    __shared__ float s_in[DD];
    const int t    = threadIdx.x;
    const int lane = t & 31;
    const int w    = t >> 5;
    const int r_start = (int)(((long long)blockIdx.x * DD) / NSM);
    const int r_end   = (int)(((long long)(blockIdx.x + 1) * DD) / NSM);
    const int nrows   = r_end - r_start;

    // ================= input layer: relu(W_in @ x + b_in) -> scatter s[0] into g_buf0
    #pragma unroll
    for (int j = t; j < DD; j += THREADS) s_in[j] = __ldg(x + j);
    __syncthreads();

    if (w < nrows) {
        const int row = r_start + w;
        const float4* __restrict__ w4 = reinterpret_cast<const float4*>(W_in + (size_t)row * DD) + lane;
        const float4* __restrict__ s4 = reinterpret_cast<const float4*>(s_in) + lane;
        float acc0 = 0.f, acc1 = 0.f;
        float4 wb[8];
        #pragma unroll
        for (int base = 0; base < 32; base += 8) {
            #pragma unroll
            for (int u = 0; u < 8; ++u) wb[u] = __ldcs(w4 + (base + u) * 32);
            #pragma unroll
            for (int u = 0; u < 8; ++u) {
                const float4 xi = s4[(base + u) * 32];
                acc0 = fmaf(wb[u].x, xi.x, acc0);
                acc1 = fmaf(wb[u].y, xi.y, acc1);
                acc0 = fmaf(wb[u].z, xi.z, acc0);
                acc1 = fmaf(wb[u].w, xi.w, acc1);
            }
        }
        float acc = acc0 + acc1;
        #pragma unroll
        for (int off = 16; off; off >>= 1) acc += __shfl_down_sync(0xffffffffu, acc, off);
        if (lane == 0) {
            float v = fmaxf(acc + __ldg(b_in + row), 0.f);
            g_buf0[__ldg(sidx + row)] = v;
        }
    }

    // prefetch front columns of masked layer 0's rows, then barrier
    {
        const float* wn = weights + (size_t)r_start * DD;
        const float* on = orders  + (size_t)r_start * DD;
        for (int idx = t; idx < nrows * 32; idx += THREADS) {
            const int r = idx >> 5, c = idx & 31;
            prefetch_l2((const char*)(wn + (size_t)r * DD) + c * 128);
            prefetch_l2((const char*)(on + (size_t)r * DD) + c * 128);
        }
    }
    grid_barrier(0);

    // ================= 4 masked layers
    float* bufs[2] = { g_buf0, g_buf1 };
    #pragma unroll 1
    for (int l = 0; l < 4; ++l) {
        const float* __restrict__ src = bufs[l & 1];
        float*       __restrict__ dst = bufs[(l & 1) ^ 1];
        const int* g = gidx + l * DD;

        // gather node values (L1 bypass: buffer was rewritten by other SMs this launch)
        #pragma unroll
        for (int j = t; j < DD; j += THREADS) s_in[j] = __ldcg(src + __ldg(g + j));
        __syncthreads();

        if (w < nrows) {
            const int row = r_start + w;
            const float4* __restrict__ w4 =
                reinterpret_cast<const float4*>(weights + (size_t)l * MATSZ + (size_t)row * DD) + lane;
            const float4* __restrict__ o4 =
                reinterpret_cast<const float4*>(orders  + (size_t)l * MATSZ + (size_t)row * DD) + lane;
            const float4* __restrict__ s4 = reinterpret_cast<const float4*>(s_in) + lane;
            float acc0 = 0.f, acc1 = 0.f;
            float4 wb[4], ob[4];
            #pragma unroll
            for (int base = 0; base < 32; base += 4) {
                #pragma unroll
                for (int u = 0; u < 4; ++u) wb[u] = __ldcs(w4 + (base + u) * 32);
                #pragma unroll
                for (int u = 0; u < 4; ++u) ob[u] = __ldcs(o4 + (base + u) * 32);
                #pragma unroll
                for (int u = 0; u < 4; ++u) {
                    const float4 xi = s4[(base + u) * 32];
                    acc0 = fmaf(wb[u].x * ob[u].x, xi.x, acc0);
                    acc1 = fmaf(wb[u].y * ob[u].y, xi.y, acc1);
                    acc0 = fmaf(wb[u].z * ob[u].z, xi.z, acc0);
                    acc1 = fmaf(wb[u].w * ob[u].w, xi.w, acc1);
                }
            }
            float acc = acc0 + acc1;
            #pragma unroll
            for (int off = 16; off; off >>= 1) acc += __shfl_down_sync(0xffffffffu, acc, off);
            if (lane == 0) {
                float v = fmaxf(acc + __ldg(biases + l * DD + row), 0.f);
                if (l < 3) dst[__ldg(sidx + (l + 1) * DD + row)] = v;
                else       out[row] = v;        // last layer: pre-scatter output
            }
        }

        if (l < 3) {
            // prefetch front columns of next layer's rows while stragglers finish
            const float* wn = weights + (size_t)(l + 1) * MATSZ + (size_t)r_start * DD;
            const float* on = orders  + (size_t)(l + 1) * MATSZ + (size_t)r_start * DD;
            for (int idx = t; idx < nrows * 32; idx += THREADS) {
                const int r = idx >> 5, c = idx & 31;
                prefetch_l2((const char*)(wn + (size_t)r * DD) + c * 128);
                prefetch_l2((const char*)(on + (size_t)r * DD) + c * 128);
            }
            grid_barrier(1 + l);
        }
    }
}

extern "C" void kernel_launch(void* const* d_in, const int* in_sizes, int n_in,
                              void* d_out, int out_size)
{
    const float* x       = (const float*)d_in[0];   // [D]
    const float* W_in    = (const float*)d_in[1];   // [D, D]
    const float* b_in    = (const float*)d_in[2];   // [D]
    const float* weights = (const float*)d_in[3];   // [L, D, D]
    const float* orders  = (const float*)d_in[4];   // [L, D, D]
    const float* biases  = (const float*)d_in[5];   // [L, D]
    const int*   gidx    = (const int*)d_in[6];     // [L, D]
    const int*   sidx    = (const int*)d_in[7];     // [L+1, D]
    float*       out     = (float*)d_out;           // [D]

    net_fused<<<NSM, THREADS>>>(x, W_in, b_in, weights, orders, biases, gidx, sidx, out);
}